// round 15
// baseline (speedup 1.0000x reference)
#include <cuda_runtime.h>
#include <cuda_fp16.h>
#include <cstdint>

// ============================================================================
// ScaledDotProductAttention  B=4 H=16 S=2048 D=128, causal, fp32 in/out
// FlashAttention-2, mma.sync.m16n8k16 HMMA.
// R14 = R13 (LPT grid, 64-key double-buffered tiles, persistent Q frags,
//       packed fp16 exp fused into P-pack, batched ldsm, full-mask skip) +
//   * diagonal MMA pruning: on diagonal chunks warp w computes only key
//     groups t <= tmax (higher groups fully masked / P exactly 0) -> exact.
//   * V first-group hoist before softmax on common path (asm volatile blocks
//     compiler reordering; manual hoist hides ldsm4t latency under exp chain).
// ============================================================================

static constexpr int SEQ = 2048;
static constexpr int DH  = 128;
static constexpr float SCALE_LOG2E = 0.08838834764831845f * 1.4426950408889634f;

static constexpr int LDH = 136;   // padded SMEM stride in halfs

// SMEM layout (half units): K 2-stage + V 2-stage; Q staged over K region.
enum : uint32_t {
    KHI_OFF = 0,                       // 2 stages x 64 rows (Q prologue overlay)
    VHI_OFF = KHI_OFF + 2 * 64 * LDH,  // 2 stages x 64 rows
    SMEM_HALVES = VHI_OFF + 2 * 64 * LDH
};
static constexpr uint32_t SMEM_BYTES = SMEM_HALVES * 2;   // 69632

// ---------------------------------------------------------------------------
__device__ __forceinline__ uint32_t cvta_s(const void* p) {
    uint32_t a;
    asm("{ .reg .u64 t; cvta.to.shared.u64 t, %1; cvt.u32.u64 %0, t; }"
        : "=r"(a) : "l"(p));
    return a;
}

__device__ __forceinline__ float ex2f(float x) {
    float r;
    asm("ex2.approx.f32 %0, %1;" : "=f"(r) : "f"(x));
    return r;
}

// packed fp16 exp2: two halves at once through one MUFU op
__device__ __forceinline__ uint32_t ex2h2(uint32_t x) {
    uint32_t r;
    asm("ex2.approx.f16x2 %0, %1;" : "=r"(r) : "r"(x));
    return r;
}

__device__ __forceinline__ void ldsm4(uint32_t r[4], uint32_t addr) {
    asm volatile("ldmatrix.sync.aligned.m8n8.x4.shared.b16 {%0,%1,%2,%3}, [%4];"
                 : "=r"(r[0]), "=r"(r[1]), "=r"(r[2]), "=r"(r[3]) : "r"(addr));
}

__device__ __forceinline__ void ldsm4t(uint32_t r[4], uint32_t addr) {
    asm volatile("ldmatrix.sync.aligned.m8n8.x4.trans.shared.b16 {%0,%1,%2,%3}, [%4];"
                 : "=r"(r[0]), "=r"(r[1]), "=r"(r[2]), "=r"(r[3]) : "r"(addr));
}

__device__ __forceinline__ void mma16816(float d[4], const uint32_t a[4],
                                         const uint32_t b[2]) {
    asm volatile(
        "mma.sync.aligned.m16n8k16.row.col.f32.f16.f16.f32 "
        "{%0,%1,%2,%3}, {%4,%5,%6,%7}, {%8,%9}, {%0,%1,%2,%3};"
        : "+f"(d[0]), "+f"(d[1]), "+f"(d[2]), "+f"(d[3])
        : "r"(a[0]), "r"(a[1]), "r"(a[2]), "r"(a[3]), "r"(b[0]), "r"(b[1]));
}

// fused f32x2 -> f16x2 convert+pack (single cvt.rn.f16x2.f32)
__device__ __forceinline__ uint32_t packf2(float a, float b) {
    __half2 h = __floats2half2_rn(a, b);
    return *reinterpret_cast<uint32_t*>(&h);
}

__device__ __forceinline__ float2 h22f2(uint32_t h) {
    __half2 v = *reinterpret_cast<__half2*>(&h);
    return __half22float2(v);
}

// ---------------------------------------------------------------------------
__global__ void __launch_bounds__(256, 1)
fa2_hmma_kernel(const float* __restrict__ Qg, const float* __restrict__ Kg,
                const float* __restrict__ Vg, float* __restrict__ Og)
{
    extern __shared__ __half sm[];
    const uint32_t sb = cvta_s(sm);
    const int tid  = threadIdx.x;
    const int w    = tid >> 5;
    const int lane = tid & 31;
    const int g    = lane >> 2;    // row group 0..7
    const int c    = lane & 3;     // col pair 0..3
    const int bh   = blockIdx.x;
    const int qt   = 15 - (int)blockIdx.y;        // heavy q-tiles first (LPT)
    const size_t base = (size_t)bh * SEQ * DH;
    const int qr0  = qt * 128;

    // ldmatrix per-lane address components
    const int a_row  = 16 * w + (lane & 7) + ((lane >> 3) & 1) * 8;
    const int a_col8 = (lane >> 4) * 8;
    const int bk_rowi = (lane & 7) + (lane >> 4) * 8;
    const int bk_col8 = ((lane >> 3) & 1) * 8;
    const int bv_rowi = (lane & 7) + ((lane >> 3) & 1) * 8;
    const int bv_col8 = (lane >> 4) * 8;

    // per-thread K/V load coordinates (8 float4 rows each, coalesced)
    const int ld_row = tid >> 5;          // 0..7 base row, step 8
    const int ld_c4  = tid & 31;          // float4 index within 128-d row

    // ---- prologue: stage Q over the K region, load persistent fragments ----
    #pragma unroll
    for (int i = 0; i < 16; i++) {
        int idx = tid + i * 256;
        int row = idx >> 5, c4 = idx & 31;
        float4 v = *(const float4*)(Qg + base + (size_t)(qr0 + row) * DH + 4 * c4);
        uint32_t p = row * LDH + 4 * c4;
        uint2 qq;
        qq.x = packf2(v.x * SCALE_LOG2E, v.y * SCALE_LOG2E);
        qq.y = packf2(v.z * SCALE_LOG2E, v.w * SCALE_LOG2E);
        *(uint2*)&sm[KHI_OFF + p] = qq;
    }
    __syncthreads();

    uint32_t qf[8][4];                    // persistent Q A-fragments
    #pragma unroll
    for (int s = 0; s < 8; s++) {
        uint32_t qa = sb + 2u * (uint32_t)(KHI_OFF + a_row * LDH + 16 * s + a_col8);
        ldsm4(qf[s], qa);
    }
    __syncthreads();                      // all warps done reading Q overlay

    const int nkt = 2 * (qt + 1);

    // ---- preload K/V tile 0 into stage 0 -----------------------------------
    #pragma unroll
    for (int i = 0; i < 8; i++) {
        int row = ld_row + 8 * i;
        size_t goff = base + (size_t)row * DH + 4 * ld_c4;
        float4 kv = *(const float4*)(Kg + goff);
        float4 vv = *(const float4*)(Vg + goff);
        uint32_t p = row * LDH + 4 * ld_c4;
        uint2 kk, vvp;
        kk.x  = packf2(kv.x, kv.y);  kk.y  = packf2(kv.z, kv.w);
        vvp.x = packf2(vv.x, vv.y);  vvp.y = packf2(vv.z, vv.w);
        *(uint2*)&sm[KHI_OFF + p] = kk;
        *(uint2*)&sm[VHI_OFF + p] = vvp;
    }

    float O_[16][4];
    #pragma unroll
    for (int n = 0; n < 16; n++)
        #pragma unroll
        for (int e = 0; e < 4; e++) O_[n][e] = 0.0f;
    float mA = -1e30f, mB = -1e30f, lA = 0.0f, lB = 0.0f;  // l thread-partial

    const int rowA = qr0 + 16 * w + g;
    const int rowB = rowA + 8;
    const int wtop = qr0 + 16 * w + 15;   // highest row this warp owns

    __syncthreads();

    for (int j = 0; j < nkt; j++) {
        const uint32_t kbuf = KHI_OFF + (uint32_t)(j & 1) * 64 * LDH;
        const uint32_t vbuf = VHI_OFF + (uint32_t)(j & 1) * 64 * LDH;

        // ---- prefetch tile j+1 into the other stage (all warps) ------------
        if (j + 1 < nkt) {
            const uint32_t kn = KHI_OFF + (uint32_t)((j + 1) & 1) * 64 * LDH;
            const uint32_t vn = VHI_OFF + (uint32_t)((j + 1) & 1) * 64 * LDH;
            #pragma unroll
            for (int i = 0; i < 8; i++) {
                int row = ld_row + 8 * i;
                size_t goff = base + (size_t)(64 * (j + 1) + row) * DH + 4 * ld_c4;
                float4 kv = *(const float4*)(Kg + goff);
                float4 vv = *(const float4*)(Vg + goff);
                uint32_t p = row * LDH + 4 * ld_c4;
                uint2 kk, vvp;
                kk.x  = packf2(kv.x, kv.y);  kk.y  = packf2(kv.z, kv.w);
                vvp.x = packf2(vv.x, vv.y);  vvp.y = packf2(vv.z, vv.w);
                *(uint2*)&sm[kn + p] = kk;
                *(uint2*)&sm[vn + p] = vvp;
            }
        }

        // ---- fully-masked chunk skip (warp-uniform; p would be exactly 0) --
        if (64 * j > wtop) {
            __syncthreads();
            continue;
        }

        const bool diag = (j >= 2 * qt);
        int tmax = 3;
        if (diag) {
            tmax = (wtop - 64 * j) >> 4;
            if (tmax > 3) tmax = 3;
        }

        // ---- S = Q K^T -----------------------------------------------------
        float S_[8][4];
        #pragma unroll
        for (int n = 0; n < 8; n++)
            #pragma unroll
            for (int e = 0; e < 4; e++) S_[n][e] = 0.0f;

        if (!diag) {
            #pragma unroll
            for (int s = 0; s < 8; s++) {
                uint32_t bhh[4][4];
                #pragma unroll
                for (int t = 0; t < 4; t++) {
                    uint32_t ka = sb + 2u * (uint32_t)(kbuf + (16 * t + bk_rowi) * LDH
                                                       + 16 * s + bk_col8);
                    ldsm4(bhh[t], ka);
                }
                #pragma unroll
                for (int t = 0; t < 4; t++) {
                    mma16816(S_[2 * t],     qf[s], bhh[t]);
                    mma16816(S_[2 * t + 1], qf[s], bhh[t] + 2);
                }
            }
        } else {
            // pruned: only key groups t <= tmax (rest fully masked anyway)
            #pragma unroll
            for (int s = 0; s < 8; s++) {
                uint32_t bhh[4][4];
                #pragma unroll
                for (int t = 0; t < 4; t++) {
                    if (t <= tmax) {
                        uint32_t ka = sb + 2u * (uint32_t)(kbuf + (16 * t + bk_rowi) * LDH
                                                           + 16 * s + bk_col8);
                        ldsm4(bhh[t], ka);
                    }
                }
                #pragma unroll
                for (int t = 0; t < 4; t++) {
                    if (t <= tmax) {
                        mma16816(S_[2 * t],     qf[s], bhh[t]);
                        mma16816(S_[2 * t + 1], qf[s], bhh[t] + 2);
                    }
                }
            }
        }

        // ---- hoisted V loads for first PV group (common path only) ---------
        uint32_t vh0[4][4];
        if (!diag) {
            #pragma unroll
            for (int t = 0; t < 4; t++) {
                uint32_t va = sb + 2u * (uint32_t)(vbuf + bv_rowi * LDH
                                                   + 16 * t + bv_col8);
                ldsm4t(vh0[t], va);
            }
        }

        // ---- causal mask (diagonal-overlap tiles only) ---------------------
        if (diag) {
            int kb = 64 * j;
            #pragma unroll
            for (int n = 0; n < 8; n++) {
                #pragma unroll
                for (int e = 0; e < 2; e++) {
                    int key = kb + 8 * n + 2 * c + e;
                    if (key > rowA) S_[n][e]     = -1e30f;
                    if (key > rowB) S_[n][2 + e] = -1e30f;
                }
            }
        }

        // ---- online softmax (quad-local max; warp-uniform rescale skip) ----
        float mtA = -1e30f, mtB = -1e30f;
        #pragma unroll
        for (int n = 0; n < 8; n++) {
            mtA = fmaxf(mtA, fmaxf(S_[n][0], S_[n][1]));
            mtB = fmaxf(mtB, fmaxf(S_[n][2], S_[n][3]));
        }
        mtA = fmaxf(mtA, __shfl_xor_sync(0xffffffffu, mtA, 1));
        mtA = fmaxf(mtA, __shfl_xor_sync(0xffffffffu, mtA, 2));
        mtB = fmaxf(mtB, __shfl_xor_sync(0xffffffffu, mtB, 1));
        mtB = fmaxf(mtB, __shfl_xor_sync(0xffffffffu, mtB, 2));

        float mnA = fmaxf(mA, mtA), mnB = fmaxf(mB, mtB);
        bool new_max = (mnA > mA) || (mnB > mB);

        if (__any_sync(0xffffffffu, new_max)) {
            float corrA = ex2f(mA - mnA), corrB = ex2f(mB - mnB);
            lA *= corrA;  lB *= corrB;
            #pragma unroll
            for (int n = 0; n < 16; n++) {
                O_[n][0] *= corrA; O_[n][1] *= corrA;
                O_[n][2] *= corrB; O_[n][3] *= corrB;
            }
            mA = mnA; mB = mnB;
        }

        // ---- fused exp + fp16 pack: P fragments straight from ex2.f16x2 ----
        uint32_t ph[4][4];
        float sA = 0.0f, sB = 0.0f;
        #pragma unroll
        for (int s = 0; s < 4; s++) {
            #pragma unroll
            for (int half_ : {0, 1}) {
                const float* src = S_[2 * s + half_];
                uint32_t e0 = ex2h2(packf2(src[0] - mA, src[1] - mA));
                uint32_t e1 = ex2h2(packf2(src[2] - mB, src[3] - mB));
                ph[s][2 * half_]     = e0;
                ph[s][2 * half_ + 1] = e1;
                float2 f0 = h22f2(e0);
                float2 f1 = h22f2(e1);
                sA += f0.x + f0.y;
                sB += f1.x + f1.y;
            }
        }
        lA += sA;  lB += sB;               // thread-partial l (from fp16 p)

        // ---- O += P V ------------------------------------------------------
        if (!diag) {
            // s = 0, first 4 d-groups from hoisted vh0
            #pragma unroll
            for (int t = 0; t < 4; t++) {
                mma16816(O_[2 * t],     ph[0], vh0[t]);
                mma16816(O_[2 * t + 1], ph[0], vh0[t] + 2);
            }
            // s = 0, d-groups 4..7
            {
                uint32_t vh[4][4];
                #pragma unroll
                for (int t = 0; t < 4; t++) {
                    int tt = 4 + t;
                    uint32_t va = sb + 2u * (uint32_t)(vbuf + bv_rowi * LDH
                                                       + 16 * tt + bv_col8);
                    ldsm4t(vh[t], va);
                }
                #pragma unroll
                for (int t = 0; t < 4; t++) {
                    int tt = 4 + t;
                    mma16816(O_[2 * tt],     ph[0], vh[t]);
                    mma16816(O_[2 * tt + 1], ph[0], vh[t] + 2);
                }
            }
            // s = 1..3
            #pragma unroll
            for (int s = 1; s < 4; s++) {
                #pragma unroll
                for (int t2 = 0; t2 < 2; t2++) {
                    uint32_t vh[4][4];
                    #pragma unroll
                    for (int t = 0; t < 4; t++) {
                        int tt = 4 * t2 + t;
                        uint32_t va = sb + 2u * (uint32_t)(vbuf + (16 * s + bv_rowi) * LDH
                                                           + 16 * tt + bv_col8);
                        ldsm4t(vh[t], va);
                    }
                    #pragma unroll
                    for (int t = 0; t < 4; t++) {
                        int tt = 4 * t2 + t;
                        mma16816(O_[2 * tt],     ph[s], vh[t]);
                        mma16816(O_[2 * tt + 1], ph[s], vh[t] + 2);
                    }
                }
            }
        } else {
            // pruned: only key groups s <= tmax (P exactly 0 beyond)
            #pragma unroll
            for (int s = 0; s < 4; s++) {
                if (s <= tmax) {
                    #pragma unroll
                    for (int t2 = 0; t2 < 2; t2++) {
                        uint32_t vh[4][4];
                        #pragma unroll
                        for (int t = 0; t < 4; t++) {
                            int tt = 4 * t2 + t;
                            uint32_t va = sb + 2u * (uint32_t)(vbuf + (16 * s + bv_rowi) * LDH
                                                               + 16 * tt + bv_col8);
                            ldsm4t(vh[t], va);
                        }
                        #pragma unroll
                        for (int t = 0; t < 4; t++) {
                            int tt = 4 * t2 + t;
                            mma16816(O_[2 * tt],     ph[s], vh[t]);
                            mma16816(O_[2 * tt + 1], ph[s], vh[t] + 2);
                        }
                    }
                }
            }
        }

        __syncthreads();   // publish prefetched tile j+1; free buffer j
    }

    // ---- epilogue: reduce l across quad, O /= l, store fp32 ----------------
    {
        lA += __shfl_xor_sync(0xffffffffu, lA, 1);
        lA += __shfl_xor_sync(0xffffffffu, lA, 2);
        lB += __shfl_xor_sync(0xffffffffu, lB, 1);
        lB += __shfl_xor_sync(0xffffffffu, lB, 2);
        float iA = 1.0f / lA, iB = 1.0f / lB;
        float* oA = Og + base + (size_t)rowA * DH;
        float* oB = oA + 8 * DH;
        #pragma unroll
        for (int n = 0; n < 16; n++) {
            *(float2*)(oA + 8 * n + 2 * c) =
                make_float2(O_[n][0] * iA, O_[n][1] * iA);
            *(float2*)(oB + 8 * n + 2 * c) =
                make_float2(O_[n][2] * iB, O_[n][3] * iB);
        }
    }
}

// ---------------------------------------------------------------------------
extern "C" void kernel_launch(void* const* d_in, const int* in_sizes, int n_in,
                              void* d_out, int out_size) {
    const float* Q = (const float*)d_in[0];
    const float* K = (const float*)d_in[1];
    const float* V = (const float*)d_in[2];
    // d_in[3] = causal mask (known tril) — applied analytically in-kernel.
    float* O = (float*)d_out;

    cudaFuncSetAttribute(fa2_hmma_kernel,
                         cudaFuncAttributeMaxDynamicSharedMemorySize, SMEM_BYTES);

    dim3 grid(64, 16, 1);   // LPT: heavy q-tiles first, bh fastest
    fa2_hmma_kernel<<<grid, 256, SMEM_BYTES>>>(Q, K, V, O);
}

// round 16
// speedup vs baseline: 1.0385x; 1.0385x over previous
#include <cuda_runtime.h>
#include <cuda_fp16.h>
#include <cstdint>

// ============================================================================
// ScaledDotProductAttention  B=4 H=16 S=2048 D=128, causal, fp32 in/out
// FlashAttention-2, mma.sync.m16n8k16 HMMA.
// R15 = R13 (LPT grid, 64-key double-buffered tiles, persistent Q frags,
//       packed fp16 exp fused into P-pack, 8B STS staging, full-mask skip)
//       + software-pipelined ldsm: two alternating fragment buffers so the
//       ldsm batch for group g+1 issues BEFORE the MMAs of group g consume
//       buffer g (each LDS batch covered by ~8 MMAs of issue).  Exact.
// R14 reverted: diag/non-diag loop duplication + V-hoist -> 233 regs, -4%.
// ============================================================================

static constexpr int SEQ = 2048;
static constexpr int DH  = 128;
static constexpr float SCALE_LOG2E = 0.08838834764831845f * 1.4426950408889634f;

static constexpr int LDH = 136;   // padded SMEM stride in halfs

// SMEM layout (half units): K 2-stage + V 2-stage; Q staged over K region.
enum : uint32_t {
    KHI_OFF = 0,                       // 2 stages x 64 rows (Q prologue overlay)
    VHI_OFF = KHI_OFF + 2 * 64 * LDH,  // 2 stages x 64 rows
    SMEM_HALVES = VHI_OFF + 2 * 64 * LDH
};
static constexpr uint32_t SMEM_BYTES = SMEM_HALVES * 2;   // 69632

// ---------------------------------------------------------------------------
__device__ __forceinline__ uint32_t cvta_s(const void* p) {
    uint32_t a;
    asm("{ .reg .u64 t; cvta.to.shared.u64 t, %1; cvt.u32.u64 %0, t; }"
        : "=r"(a) : "l"(p));
    return a;
}

__device__ __forceinline__ float ex2f(float x) {
    float r;
    asm("ex2.approx.f32 %0, %1;" : "=f"(r) : "f"(x));
    return r;
}

// packed fp16 exp2: two halves at once through one MUFU op
__device__ __forceinline__ uint32_t ex2h2(uint32_t x) {
    uint32_t r;
    asm("ex2.approx.f16x2 %0, %1;" : "=r"(r) : "r"(x));
    return r;
}

__device__ __forceinline__ void ldsm4(uint32_t r[4], uint32_t addr) {
    asm volatile("ldmatrix.sync.aligned.m8n8.x4.shared.b16 {%0,%1,%2,%3}, [%4];"
                 : "=r"(r[0]), "=r"(r[1]), "=r"(r[2]), "=r"(r[3]) : "r"(addr));
}

__device__ __forceinline__ void ldsm4t(uint32_t r[4], uint32_t addr) {
    asm volatile("ldmatrix.sync.aligned.m8n8.x4.trans.shared.b16 {%0,%1,%2,%3}, [%4];"
                 : "=r"(r[0]), "=r"(r[1]), "=r"(r[2]), "=r"(r[3]) : "r"(addr));
}

__device__ __forceinline__ void mma16816(float d[4], const uint32_t a[4],
                                         const uint32_t b[2]) {
    asm volatile(
        "mma.sync.aligned.m16n8k16.row.col.f32.f16.f16.f32 "
        "{%0,%1,%2,%3}, {%4,%5,%6,%7}, {%8,%9}, {%0,%1,%2,%3};"
        : "+f"(d[0]), "+f"(d[1]), "+f"(d[2]), "+f"(d[3])
        : "r"(a[0]), "r"(a[1]), "r"(a[2]), "r"(a[3]), "r"(b[0]), "r"(b[1]));
}

// fused f32x2 -> f16x2 convert+pack (single cvt.rn.f16x2.f32)
__device__ __forceinline__ uint32_t packf2(float a, float b) {
    __half2 h = __floats2half2_rn(a, b);
    return *reinterpret_cast<uint32_t*>(&h);
}

__device__ __forceinline__ float2 h22f2(uint32_t h) {
    __half2 v = *reinterpret_cast<__half2*>(&h);
    return __half22float2(v);
}

// ---------------------------------------------------------------------------
__global__ void __launch_bounds__(256, 1)
fa2_hmma_kernel(const float* __restrict__ Qg, const float* __restrict__ Kg,
                const float* __restrict__ Vg, float* __restrict__ Og)
{
    extern __shared__ __half sm[];
    const uint32_t sb = cvta_s(sm);
    const int tid  = threadIdx.x;
    const int w    = tid >> 5;
    const int lane = tid & 31;
    const int g    = lane >> 2;    // row group 0..7
    const int c    = lane & 3;     // col pair 0..3
    const int bh   = blockIdx.x;
    const int qt   = 15 - (int)blockIdx.y;        // heavy q-tiles first (LPT)
    const size_t base = (size_t)bh * SEQ * DH;
    const int qr0  = qt * 128;

    // ldmatrix per-lane address components
    const int a_row  = 16 * w + (lane & 7) + ((lane >> 3) & 1) * 8;
    const int a_col8 = (lane >> 4) * 8;
    const int bk_rowi = (lane & 7) + (lane >> 4) * 8;
    const int bk_col8 = ((lane >> 3) & 1) * 8;
    const int bv_rowi = (lane & 7) + ((lane >> 3) & 1) * 8;
    const int bv_col8 = (lane >> 4) * 8;

    // per-thread K/V load coordinates (8 float4 rows each, coalesced)
    const int ld_row = tid >> 5;          // 0..7 base row, step 8
    const int ld_c4  = tid & 31;          // float4 index within 128-d row

    // ---- prologue: stage Q over the K region, load persistent fragments ----
    #pragma unroll
    for (int i = 0; i < 16; i++) {
        int idx = tid + i * 256;
        int row = idx >> 5, c4 = idx & 31;
        float4 v = *(const float4*)(Qg + base + (size_t)(qr0 + row) * DH + 4 * c4);
        uint32_t p = row * LDH + 4 * c4;
        uint2 qq;
        qq.x = packf2(v.x * SCALE_LOG2E, v.y * SCALE_LOG2E);
        qq.y = packf2(v.z * SCALE_LOG2E, v.w * SCALE_LOG2E);
        *(uint2*)&sm[KHI_OFF + p] = qq;
    }
    __syncthreads();

    uint32_t qf[8][4];                    // persistent Q A-fragments
    #pragma unroll
    for (int s = 0; s < 8; s++) {
        uint32_t qa = sb + 2u * (uint32_t)(KHI_OFF + a_row * LDH + 16 * s + a_col8);
        ldsm4(qf[s], qa);
    }
    __syncthreads();                      // all warps done reading Q overlay

    const int nkt = 2 * (qt + 1);

    // ---- preload K/V tile 0 into stage 0 -----------------------------------
    #pragma unroll
    for (int i = 0; i < 8; i++) {
        int row = ld_row + 8 * i;
        size_t goff = base + (size_t)row * DH + 4 * ld_c4;
        float4 kv = *(const float4*)(Kg + goff);
        float4 vv = *(const float4*)(Vg + goff);
        uint32_t p = row * LDH + 4 * ld_c4;
        uint2 kk, vvp;
        kk.x  = packf2(kv.x, kv.y);  kk.y  = packf2(kv.z, kv.w);
        vvp.x = packf2(vv.x, vv.y);  vvp.y = packf2(vv.z, vv.w);
        *(uint2*)&sm[KHI_OFF + p] = kk;
        *(uint2*)&sm[VHI_OFF + p] = vvp;
    }

    float O_[16][4];
    #pragma unroll
    for (int n = 0; n < 16; n++)
        #pragma unroll
        for (int e = 0; e < 4; e++) O_[n][e] = 0.0f;
    float mA = -1e30f, mB = -1e30f, lA = 0.0f, lB = 0.0f;  // l thread-partial

    const int rowA = qr0 + 16 * w + g;
    const int rowB = rowA + 8;
    const int wtop = qr0 + 16 * w + 15;   // highest row this warp owns

    __syncthreads();

    for (int j = 0; j < nkt; j++) {
        const uint32_t kbuf = KHI_OFF + (uint32_t)(j & 1) * 64 * LDH;
        const uint32_t vbuf = VHI_OFF + (uint32_t)(j & 1) * 64 * LDH;

        // ---- prefetch tile j+1 into the other stage (all warps) ------------
        if (j + 1 < nkt) {
            const uint32_t kn = KHI_OFF + (uint32_t)((j + 1) & 1) * 64 * LDH;
            const uint32_t vn = VHI_OFF + (uint32_t)((j + 1) & 1) * 64 * LDH;
            #pragma unroll
            for (int i = 0; i < 8; i++) {
                int row = ld_row + 8 * i;
                size_t goff = base + (size_t)(64 * (j + 1) + row) * DH + 4 * ld_c4;
                float4 kv = *(const float4*)(Kg + goff);
                float4 vv = *(const float4*)(Vg + goff);
                uint32_t p = row * LDH + 4 * ld_c4;
                uint2 kk, vvp;
                kk.x  = packf2(kv.x, kv.y);  kk.y  = packf2(kv.z, kv.w);
                vvp.x = packf2(vv.x, vv.y);  vvp.y = packf2(vv.z, vv.w);
                *(uint2*)&sm[kn + p] = kk;
                *(uint2*)&sm[vn + p] = vvp;
            }
        }

        // ---- fully-masked chunk skip (warp-uniform; p would be exactly 0) --
        if (64 * j > wtop) {
            __syncthreads();
            continue;
        }

        // ---- S = Q K^T  (ldsm double-buffered across k-steps) --------------
        float S_[8][4];
        #pragma unroll
        for (int n = 0; n < 8; n++)
            #pragma unroll
            for (int e = 0; e < 4; e++) S_[n][e] = 0.0f;

        {
            uint32_t bA[4][4], bB[4][4];
            // preload k-step 0 batch
            #pragma unroll
            for (int t = 0; t < 4; t++) {
                uint32_t ka = sb + 2u * (uint32_t)(kbuf + (16 * t + bk_rowi) * LDH
                                                   + bk_col8);
                ldsm4(bA[t], ka);
            }
            #pragma unroll
            for (int s = 0; s < 8; s++) {
                uint32_t (*cur)[4] = (s & 1) ? bB : bA;
                uint32_t (*nxt)[4] = (s & 1) ? bA : bB;
                if (s < 7) {
                    #pragma unroll
                    for (int t = 0; t < 4; t++) {
                        uint32_t ka = sb + 2u * (uint32_t)(kbuf + (16 * t + bk_rowi) * LDH
                                                           + 16 * (s + 1) + bk_col8);
                        ldsm4(nxt[t], ka);
                    }
                }
                #pragma unroll
                for (int t = 0; t < 4; t++) {
                    mma16816(S_[2 * t],     qf[s], cur[t]);
                    mma16816(S_[2 * t + 1], qf[s], cur[t] + 2);
                }
            }
        }

        // ---- causal mask (diagonal-overlap tiles only) ---------------------
        if (j >= 2 * qt) {
            int kb = 64 * j;
            #pragma unroll
            for (int n = 0; n < 8; n++) {
                #pragma unroll
                for (int e = 0; e < 2; e++) {
                    int key = kb + 8 * n + 2 * c + e;
                    if (key > rowA) S_[n][e]     = -1e30f;
                    if (key > rowB) S_[n][2 + e] = -1e30f;
                }
            }
        }

        // ---- online softmax (quad-local max; warp-uniform rescale skip) ----
        float mtA = -1e30f, mtB = -1e30f;
        #pragma unroll
        for (int n = 0; n < 8; n++) {
            mtA = fmaxf(mtA, fmaxf(S_[n][0], S_[n][1]));
            mtB = fmaxf(mtB, fmaxf(S_[n][2], S_[n][3]));
        }
        mtA = fmaxf(mtA, __shfl_xor_sync(0xffffffffu, mtA, 1));
        mtA = fmaxf(mtA, __shfl_xor_sync(0xffffffffu, mtA, 2));
        mtB = fmaxf(mtB, __shfl_xor_sync(0xffffffffu, mtB, 1));
        mtB = fmaxf(mtB, __shfl_xor_sync(0xffffffffu, mtB, 2));

        float mnA = fmaxf(mA, mtA), mnB = fmaxf(mB, mtB);
        bool new_max = (mnA > mA) || (mnB > mB);

        if (__any_sync(0xffffffffu, new_max)) {
            float corrA = ex2f(mA - mnA), corrB = ex2f(mB - mnB);
            lA *= corrA;  lB *= corrB;
            #pragma unroll
            for (int n = 0; n < 16; n++) {
                O_[n][0] *= corrA; O_[n][1] *= corrA;
                O_[n][2] *= corrB; O_[n][3] *= corrB;
            }
            mA = mnA; mB = mnB;
        }
        // else: corr == 1 exactly; nothing to do.

        // ---- fused exp + fp16 pack: P fragments straight from ex2.f16x2 ----
        uint32_t ph[4][4];
        float sA = 0.0f, sB = 0.0f;
        #pragma unroll
        for (int s = 0; s < 4; s++) {
            #pragma unroll
            for (int half_ : {0, 1}) {
                const float* src = S_[2 * s + half_];
                uint32_t e0 = ex2h2(packf2(src[0] - mA, src[1] - mA));
                uint32_t e1 = ex2h2(packf2(src[2] - mB, src[3] - mB));
                ph[s][2 * half_]     = e0;
                ph[s][2 * half_ + 1] = e1;
                float2 f0 = h22f2(e0);
                float2 f1 = h22f2(e1);
                sA += f0.x + f0.y;
                sB += f1.x + f1.y;
            }
        }
        lA += sA;  lB += sB;               // thread-partial l (from fp16 p)

        // ---- O += P V  (ldsm double-buffered across the 8 groups) ----------
        {
            uint32_t vA[4][4], vB[4][4];
            // group gidx = 0..7 maps to s = gidx>>1, t-block = gidx&1
            #pragma unroll
            for (int t = 0; t < 4; t++) {
                uint32_t va = sb + 2u * (uint32_t)(vbuf + bv_rowi * LDH
                                                   + 16 * t + bv_col8);
                ldsm4t(vA[t], va);
            }
            #pragma unroll
            for (int gidx = 0; gidx < 8; gidx++) {
                uint32_t (*cur)[4] = (gidx & 1) ? vB : vA;
                uint32_t (*nxt)[4] = (gidx & 1) ? vA : vB;
                if (gidx < 7) {
                    int ns  = (gidx + 1) >> 1;
                    int nt2 = (gidx + 1) & 1;
                    #pragma unroll
                    for (int t = 0; t < 4; t++) {
                        int tt = 4 * nt2 + t;
                        uint32_t va = sb + 2u * (uint32_t)(vbuf + (16 * ns + bv_rowi) * LDH
                                                           + 16 * tt + bv_col8);
                        ldsm4t(nxt[t], va);
                    }
                }
                int s  = gidx >> 1;
                int t2 = gidx & 1;
                #pragma unroll
                for (int t = 0; t < 4; t++) {
                    int tt = 4 * t2 + t;
                    mma16816(O_[2 * tt],     ph[s], cur[t]);
                    mma16816(O_[2 * tt + 1], ph[s], cur[t] + 2);
                }
            }
        }

        __syncthreads();   // publish prefetched tile j+1; free buffer j
    }

    // ---- epilogue: reduce l across quad, O /= l, store fp32 ----------------
    {
        lA += __shfl_xor_sync(0xffffffffu, lA, 1);
        lA += __shfl_xor_sync(0xffffffffu, lA, 2);
        lB += __shfl_xor_sync(0xffffffffu, lB, 1);
        lB += __shfl_xor_sync(0xffffffffu, lB, 2);
        float iA = 1.0f / lA, iB = 1.0f / lB;
        float* oA = Og + base + (size_t)rowA * DH;
        float* oB = oA + 8 * DH;
        #pragma unroll
        for (int n = 0; n < 16; n++) {
            *(float2*)(oA + 8 * n + 2 * c) =
                make_float2(O_[n][0] * iA, O_[n][1] * iA);
            *(float2*)(oB + 8 * n + 2 * c) =
                make_float2(O_[n][2] * iB, O_[n][3] * iB);
        }
    }
}

// ---------------------------------------------------------------------------
extern "C" void kernel_launch(void* const* d_in, const int* in_sizes, int n_in,
                              void* d_out, int out_size) {
    const float* Q = (const float*)d_in[0];
    const float* K = (const float*)d_in[1];
    const float* V = (const float*)d_in[2];
    // d_in[3] = causal mask (known tril) — applied analytically in-kernel.
    float* O = (float*)d_out;

    cudaFuncSetAttribute(fa2_hmma_kernel,
                         cudaFuncAttributeMaxDynamicSharedMemorySize, SMEM_BYTES);

    dim3 grid(64, 16, 1);   // LPT: heavy q-tiles first, bh fastest
    fa2_hmma_kernel<<<grid, 256, SMEM_BYTES>>>(Q, K, V, O);
}

// round 17
// speedup vs baseline: 1.0472x; 1.0083x over previous
#include <cuda_runtime.h>
#include <cuda_fp16.h>
#include <cstdint>

// ============================================================================
// ScaledDotProductAttention  B=4 H=16 S=2048 D=128, causal, fp32 in/out
// FlashAttention-2, mma.sync.m16n8k16 HMMA.
// R16 = R13 (LPT grid, persistent Q frags, packed fp16 exp fused into P-pack,
//       batched ldsm, full-mask skip, thread-partial l) with the K/V double
//       buffer widened to a 4-slot ring (4 x 64-row K, 4 x 64-row V) and
//       __syncthreads() only after odd chunks: half the barriers, half the
//       warp-skew convergence tax. Prefetch distance 2 chunks.
//       Ring safety: R(4) >= D(2) + P(2).  Zero arithmetic change.
// ============================================================================

static constexpr int SEQ = 2048;
static constexpr int DH  = 128;
static constexpr float SCALE_LOG2E = 0.08838834764831845f * 1.4426950408889634f;

static constexpr int LDH = 136;   // padded SMEM stride in halfs

// SMEM layout (half units): 4-slot K ring + 4-slot V ring; Q staged over K.
enum : uint32_t {
    KHI_OFF = 0,                       // 4 slots x 64 rows (Q overlay on 0..1)
    VHI_OFF = KHI_OFF + 4 * 64 * LDH,  // 4 slots x 64 rows
    SMEM_HALVES = VHI_OFF + 4 * 64 * LDH
};
static constexpr uint32_t SMEM_BYTES = SMEM_HALVES * 2;   // 139264

// ---------------------------------------------------------------------------
__device__ __forceinline__ uint32_t cvta_s(const void* p) {
    uint32_t a;
    asm("{ .reg .u64 t; cvta.to.shared.u64 t, %1; cvt.u32.u64 %0, t; }"
        : "=r"(a) : "l"(p));
    return a;
}

__device__ __forceinline__ float ex2f(float x) {
    float r;
    asm("ex2.approx.f32 %0, %1;" : "=f"(r) : "f"(x));
    return r;
}

// packed fp16 exp2: two halves at once through one MUFU op
__device__ __forceinline__ uint32_t ex2h2(uint32_t x) {
    uint32_t r;
    asm("ex2.approx.f16x2 %0, %1;" : "=r"(r) : "r"(x));
    return r;
}

__device__ __forceinline__ void ldsm4(uint32_t r[4], uint32_t addr) {
    asm volatile("ldmatrix.sync.aligned.m8n8.x4.shared.b16 {%0,%1,%2,%3}, [%4];"
                 : "=r"(r[0]), "=r"(r[1]), "=r"(r[2]), "=r"(r[3]) : "r"(addr));
}

__device__ __forceinline__ void ldsm4t(uint32_t r[4], uint32_t addr) {
    asm volatile("ldmatrix.sync.aligned.m8n8.x4.trans.shared.b16 {%0,%1,%2,%3}, [%4];"
                 : "=r"(r[0]), "=r"(r[1]), "=r"(r[2]), "=r"(r[3]) : "r"(addr));
}

__device__ __forceinline__ void mma16816(float d[4], const uint32_t a[4],
                                         const uint32_t b[2]) {
    asm volatile(
        "mma.sync.aligned.m16n8k16.row.col.f32.f16.f16.f32 "
        "{%0,%1,%2,%3}, {%4,%5,%6,%7}, {%8,%9}, {%0,%1,%2,%3};"
        : "+f"(d[0]), "+f"(d[1]), "+f"(d[2]), "+f"(d[3])
        : "r"(a[0]), "r"(a[1]), "r"(a[2]), "r"(a[3]), "r"(b[0]), "r"(b[1]));
}

// fused f32x2 -> f16x2 convert+pack (single cvt.rn.f16x2.f32)
__device__ __forceinline__ uint32_t packf2(float a, float b) {
    __half2 h = __floats2half2_rn(a, b);
    return *reinterpret_cast<uint32_t*>(&h);
}

__device__ __forceinline__ float2 h22f2(uint32_t h) {
    __half2 v = *reinterpret_cast<__half2*>(&h);
    return __half22float2(v);
}

// ---------------------------------------------------------------------------
__global__ void __launch_bounds__(256, 1)
fa2_hmma_kernel(const float* __restrict__ Qg, const float* __restrict__ Kg,
                const float* __restrict__ Vg, float* __restrict__ Og)
{
    extern __shared__ __half sm[];
    const uint32_t sb = cvta_s(sm);
    const int tid  = threadIdx.x;
    const int w    = tid >> 5;
    const int lane = tid & 31;
    const int g    = lane >> 2;    // row group 0..7
    const int c    = lane & 3;     // col pair 0..3
    const int bh   = blockIdx.x;
    const int qt   = 15 - (int)blockIdx.y;        // heavy q-tiles first (LPT)
    const size_t base = (size_t)bh * SEQ * DH;
    const int qr0  = qt * 128;

    // ldmatrix per-lane address components
    const int a_row  = 16 * w + (lane & 7) + ((lane >> 3) & 1) * 8;
    const int a_col8 = (lane >> 4) * 8;
    const int bk_rowi = (lane & 7) + (lane >> 4) * 8;
    const int bk_col8 = ((lane >> 3) & 1) * 8;
    const int bv_rowi = (lane & 7) + ((lane >> 3) & 1) * 8;
    const int bv_col8 = (lane >> 4) * 8;

    // per-thread K/V load coordinates (8 float4 rows each, coalesced)
    const int ld_row = tid >> 5;          // 0..7 base row, step 8
    const int ld_c4  = tid & 31;          // float4 index within 128-d row

    // ---- prologue: stage Q over the K ring (slots 0..1), load fragments ----
    #pragma unroll
    for (int i = 0; i < 16; i++) {
        int idx = tid + i * 256;
        int row = idx >> 5, c4 = idx & 31;
        float4 v = *(const float4*)(Qg + base + (size_t)(qr0 + row) * DH + 4 * c4);
        uint32_t p = row * LDH + 4 * c4;
        uint2 qq;
        qq.x = packf2(v.x * SCALE_LOG2E, v.y * SCALE_LOG2E);
        qq.y = packf2(v.z * SCALE_LOG2E, v.w * SCALE_LOG2E);
        *(uint2*)&sm[KHI_OFF + p] = qq;
    }
    __syncthreads();

    uint32_t qf[8][4];                    // persistent Q A-fragments
    #pragma unroll
    for (int s = 0; s < 8; s++) {
        uint32_t qa = sb + 2u * (uint32_t)(KHI_OFF + a_row * LDH + 16 * s + a_col8);
        ldsm4(qf[s], qa);
    }
    __syncthreads();                      // all warps done reading Q overlay

    const int nkt = 2 * (qt + 1);

    // ---- preload chunks 0 and 1 into ring slots 0 and 1 --------------------
    #pragma unroll 1
    for (int ch = 0; ch < 2; ch++) {
        const uint32_t ks = KHI_OFF + (uint32_t)ch * 64 * LDH;
        const uint32_t vs = VHI_OFF + (uint32_t)ch * 64 * LDH;
        #pragma unroll
        for (int i = 0; i < 8; i++) {
            int row = ld_row + 8 * i;
            size_t goff = base + (size_t)(64 * ch + row) * DH + 4 * ld_c4;
            float4 kv = *(const float4*)(Kg + goff);
            float4 vv = *(const float4*)(Vg + goff);
            uint32_t p = row * LDH + 4 * ld_c4;
            uint2 kk, vvp;
            kk.x  = packf2(kv.x, kv.y);  kk.y  = packf2(kv.z, kv.w);
            vvp.x = packf2(vv.x, vv.y);  vvp.y = packf2(vv.z, vv.w);
            *(uint2*)&sm[ks + p] = kk;
            *(uint2*)&sm[vs + p] = vvp;
        }
    }

    float O_[16][4];
    #pragma unroll
    for (int n = 0; n < 16; n++)
        #pragma unroll
        for (int e = 0; e < 4; e++) O_[n][e] = 0.0f;
    float mA = -1e30f, mB = -1e30f, lA = 0.0f, lB = 0.0f;  // l thread-partial

    const int rowA = qr0 + 16 * w + g;
    const int rowB = rowA + 8;
    const int wtop = qr0 + 16 * w + 15;   // highest row this warp owns

    __syncthreads();

    for (int j = 0; j < nkt; j++) {
        const uint32_t kbuf = KHI_OFF + (uint32_t)(j & 3) * 64 * LDH;
        const uint32_t vbuf = VHI_OFF + (uint32_t)(j & 3) * 64 * LDH;

        // ---- prefetch chunk j+2 into ring slot (j+2)&3 (all warps) ---------
        if (j + 2 < nkt) {
            const uint32_t kn = KHI_OFF + (uint32_t)((j + 2) & 3) * 64 * LDH;
            const uint32_t vn = VHI_OFF + (uint32_t)((j + 2) & 3) * 64 * LDH;
            #pragma unroll
            for (int i = 0; i < 8; i++) {
                int row = ld_row + 8 * i;
                size_t goff = base + (size_t)(64 * (j + 2) + row) * DH + 4 * ld_c4;
                float4 kv = *(const float4*)(Kg + goff);
                float4 vv = *(const float4*)(Vg + goff);
                uint32_t p = row * LDH + 4 * ld_c4;
                uint2 kk, vvp;
                kk.x  = packf2(kv.x, kv.y);  kk.y  = packf2(kv.z, kv.w);
                vvp.x = packf2(vv.x, vv.y);  vvp.y = packf2(vv.z, vv.w);
                *(uint2*)&sm[kn + p] = kk;
                *(uint2*)&sm[vn + p] = vvp;
            }
        }

        // ---- fully-masked chunk skip (warp-uniform; p would be exactly 0) --
        if (64 * j > wtop) {
            if (j & 1) __syncthreads();
            continue;
        }

        // ---- S = Q K^T  (batched ldsm: 4 K-frags, then 8 MMAs) -------------
        float S_[8][4];
        #pragma unroll
        for (int n = 0; n < 8; n++)
            #pragma unroll
            for (int e = 0; e < 4; e++) S_[n][e] = 0.0f;

        #pragma unroll
        for (int s = 0; s < 8; s++) {
            uint32_t bhh[4][4];
            #pragma unroll
            for (int t = 0; t < 4; t++) {
                uint32_t ka = sb + 2u * (uint32_t)(kbuf + (16 * t + bk_rowi) * LDH
                                                   + 16 * s + bk_col8);
                ldsm4(bhh[t], ka);
            }
            #pragma unroll
            for (int t = 0; t < 4; t++) {
                mma16816(S_[2 * t],     qf[s], bhh[t]);
                mma16816(S_[2 * t + 1], qf[s], bhh[t] + 2);
            }
        }

        // ---- causal mask (diagonal-overlap tiles only) ---------------------
        if (j >= 2 * qt) {
            int kb = 64 * j;
            #pragma unroll
            for (int n = 0; n < 8; n++) {
                #pragma unroll
                for (int e = 0; e < 2; e++) {
                    int key = kb + 8 * n + 2 * c + e;
                    if (key > rowA) S_[n][e]     = -1e30f;
                    if (key > rowB) S_[n][2 + e] = -1e30f;
                }
            }
        }

        // ---- online softmax (quad-local max; warp-uniform rescale skip) ----
        float mtA = -1e30f, mtB = -1e30f;
        #pragma unroll
        for (int n = 0; n < 8; n++) {
            mtA = fmaxf(mtA, fmaxf(S_[n][0], S_[n][1]));
            mtB = fmaxf(mtB, fmaxf(S_[n][2], S_[n][3]));
        }
        mtA = fmaxf(mtA, __shfl_xor_sync(0xffffffffu, mtA, 1));
        mtA = fmaxf(mtA, __shfl_xor_sync(0xffffffffu, mtA, 2));
        mtB = fmaxf(mtB, __shfl_xor_sync(0xffffffffu, mtB, 1));
        mtB = fmaxf(mtB, __shfl_xor_sync(0xffffffffu, mtB, 2));

        float mnA = fmaxf(mA, mtA), mnB = fmaxf(mB, mtB);
        bool new_max = (mnA > mA) || (mnB > mB);

        if (__any_sync(0xffffffffu, new_max)) {
            float corrA = ex2f(mA - mnA), corrB = ex2f(mB - mnB);
            lA *= corrA;  lB *= corrB;
            #pragma unroll
            for (int n = 0; n < 16; n++) {
                O_[n][0] *= corrA; O_[n][1] *= corrA;
                O_[n][2] *= corrB; O_[n][3] *= corrB;
            }
            mA = mnA; mB = mnB;
        }
        // else: corr == 1 exactly; nothing to do.

        // ---- fused exp + fp16 pack: P fragments straight from ex2.f16x2 ----
        uint32_t ph[4][4];
        float sA = 0.0f, sB = 0.0f;
        #pragma unroll
        for (int s = 0; s < 4; s++) {
            #pragma unroll
            for (int half_ : {0, 1}) {
                const float* src = S_[2 * s + half_];
                uint32_t e0 = ex2h2(packf2(src[0] - mA, src[1] - mA));
                uint32_t e1 = ex2h2(packf2(src[2] - mB, src[3] - mB));
                ph[s][2 * half_]     = e0;
                ph[s][2 * half_ + 1] = e1;
                float2 f0 = h22f2(e0);
                float2 f1 = h22f2(e1);
                sA += f0.x + f0.y;
                sB += f1.x + f1.y;
            }
        }
        lA += sA;  lB += sB;               // thread-partial l (from fp16 p)

        // ---- O += P V  (batched ldsm: 4 V-frags, then 8 MMAs) --------------
        #pragma unroll
        for (int s = 0; s < 4; s++) {
            #pragma unroll
            for (int t2 = 0; t2 < 2; t2++) {
                uint32_t vh[4][4];
                #pragma unroll
                for (int t = 0; t < 4; t++) {
                    int tt = 4 * t2 + t;
                    uint32_t va = sb + 2u * (uint32_t)(vbuf + (16 * s + bv_rowi) * LDH
                                                       + 16 * tt + bv_col8);
                    ldsm4t(vh[t], va);
                }
                #pragma unroll
                for (int t = 0; t < 4; t++) {
                    int tt = 4 * t2 + t;
                    mma16816(O_[2 * tt],     ph[s], vh[t]);
                    mma16816(O_[2 * tt + 1], ph[s], vh[t] + 2);
                }
            }
        }

        if (j & 1) __syncthreads();   // publish the two prefetched chunks;
                                      // free the macro stage just consumed
    }

    // ---- epilogue: reduce l across quad, O /= l, store fp32 ----------------
    {
        lA += __shfl_xor_sync(0xffffffffu, lA, 1);
        lA += __shfl_xor_sync(0xffffffffu, lA, 2);
        lB += __shfl_xor_sync(0xffffffffu, lB, 1);
        lB += __shfl_xor_sync(0xffffffffu, lB, 2);
        float iA = 1.0f / lA, iB = 1.0f / lB;
        float* oA = Og + base + (size_t)rowA * DH;
        float* oB = oA + 8 * DH;
        #pragma unroll
        for (int n = 0; n < 16; n++) {
            *(float2*)(oA + 8 * n + 2 * c) =
                make_float2(O_[n][0] * iA, O_[n][1] * iA);
            *(float2*)(oB + 8 * n + 2 * c) =
                make_float2(O_[n][2] * iB, O_[n][3] * iB);
        }
    }
}

// ---------------------------------------------------------------------------
extern "C" void kernel_launch(void* const* d_in, const int* in_sizes, int n_in,
                              void* d_out, int out_size) {
    const float* Q = (const float*)d_in[0];
    const float* K = (const float*)d_in[1];
    const float* V = (const float*)d_in[2];
    // d_in[3] = causal mask (known tril) — applied analytically in-kernel.
    float* O = (float*)d_out;

    cudaFuncSetAttribute(fa2_hmma_kernel,
                         cudaFuncAttributeMaxDynamicSharedMemorySize, SMEM_BYTES);

    dim3 grid(64, 16, 1);   // LPT: heavy q-tiles first, bh fastest
    fa2_hmma_kernel<<<grid, 256, SMEM_BYTES>>>(Q, K, V, O);
}